// round 15
// baseline (speedup 1.0000x reference)
#include <cuda_runtime.h>
#include <cuda_bf16.h>
#include <cstdint>

// ---------------- device scratch (globals — allowed) ----------------
__device__ __nv_bfloat16 g_Ebf[98304UL * 1024];   // E in bf16, row-major
__device__ __nv_bfloat16 g_Wt[8 * 256 * 1024];    // [head][n (Q0..127|K128..255)][k]
__device__ float         g_gate[16384 * 6];

namespace {

constexpr int  kSamples = 16384;
constexpr long kRows    = 98304;               // 16384*6
constexpr int  SPC      = 10;                  // samples per CTA tile (60 rows, pad 64)
constexpr int  MTILES   = (kSamples + SPC - 1) / SPC;  // 1639
constexpr int  TCH      = 32;                  // 2 heads x 16 chunks, continuous
constexpr int  STAGE    = 40960;               // A 8KB + B 32KB
constexpr int  BOFF     = 8192;                // B within stage
constexpr uint32_t QKO   = 81920;              // bf16 qk, separate from stages
constexpr int  QKS2     = 258;                 // qk stride in bf16 elems (even)
constexpr uint32_t BIASO = 112896;             // QKO + 60*258*2 (30960) + pad
constexpr uint32_t SCO   = 113920;             // BIASO + 1024
constexpr int  SMEM_TOTAL = 115360;            // 2 CTAs/SM

__device__ __forceinline__ uint32_t smem_u32(const void* p) {
  return (uint32_t)__cvta_generic_to_shared(p);
}
__device__ __forceinline__ void cpa16(uint32_t dst, const void* src, int sz) {
  asm volatile("cp.async.cg.shared.global [%0], [%1], 16, %2;\n"
               :: "r"(dst), "l"(src), "r"(sz));
}
__device__ __forceinline__ void ldsm4(uint32_t* r, uint32_t addr) {
  asm volatile("ldmatrix.sync.aligned.m8n8.x4.shared.b16 {%0,%1,%2,%3}, [%4];"
               : "=r"(r[0]), "=r"(r[1]), "=r"(r[2]), "=r"(r[3]) : "r"(addr));
}
__device__ __forceinline__ void mma_bf16(float* d, const uint32_t* a, const uint32_t* b) {
  asm volatile(
      "mma.sync.aligned.m16n8k16.row.col.f32.bf16.bf16.f32 "
      "{%0,%1,%2,%3}, {%4,%5,%6,%7}, {%8,%9}, {%0,%1,%2,%3};\n"
      : "+f"(d[0]), "+f"(d[1]), "+f"(d[2]), "+f"(d[3])
      : "r"(a[0]), "r"(a[1]), "r"(a[2]), "r"(a[3]), "r"(b[0]), "r"(b[1]));
}

}  // namespace

// ---------------- pre-pass kernels ----------------
__global__ void conv_e_kernel(const float* __restrict__ emb) {
  const long total = kRows * 1024 / 8;
  for (long i = blockIdx.x * 256L + threadIdx.x; i < total; i += (long)gridDim.x * 256) {
    const float4* s = (const float4*)emb + i * 2;
    float4 a = s[0], b = s[1];
    __nv_bfloat162* o = (__nv_bfloat162*)g_Ebf + i * 4;
    o[0] = __floats2bfloat162_rn(a.x, a.y);
    o[1] = __floats2bfloat162_rn(a.z, a.w);
    o[2] = __floats2bfloat162_rn(b.x, b.y);
    o[3] = __floats2bfloat162_rn(b.z, b.w);
  }
}

__global__ void conv_w_kernel(const float* __restrict__ Wq, const float* __restrict__ Wk) {
  const int idx = blockIdx.x * 256 + threadIdx.x;  // 262144 total
  const int h  = idx >> 15;
  const int n  = (idx >> 7) & 255;
  const int k0 = (idx & 127) * 8;
  const float* W = (n < 128) ? Wq : Wk;
  const int col = h * 128 + (n & 127);
  __nv_bfloat16* o = g_Wt + ((long)(h * 256 + n)) * 1024 + k0;
#pragma unroll
  for (int t = 0; t < 8; t++) o[t] = __float2bfloat16(W[(long)(k0 + t) * 1024 + col]);
}

__global__ void gate_kernel(const float* __restrict__ ac, const float* __restrict__ Wg,
                            const float* __restrict__ bg) {
  const int idx = blockIdx.x * 256 + threadIdx.x;  // 98304
  const int s = idx / 6, j = idx % 6;
  const float* ap = ac + (long)s * 128;
  float g = bg[j];
#pragma unroll 8
  for (int c = 0; c < 128; c++) g = fmaf(ap[c], Wg[c * 6 + j], g);
  g_gate[idx] = g;
}

// ------- main fused kernel: one (mtile, head-pair) per CTA, 2 CTAs/SM -------
__global__ void __launch_bounds__(256, 2)
attn_main_kernel(const float* __restrict__ emb, const float* __restrict__ bk,
                 const float* __restrict__ bq, float* __restrict__ ctx,
                 float* __restrict__ att) {
  extern __shared__ char smc[];
  const uint32_t sb = smem_u32(smc);
  __nv_bfloat16* qkb = (__nv_bfloat16*)(smc + QKO);
  float* bia = (float*)(smc + BIASO);
  float* sc  = (float*)(smc + SCO);

  const int tid  = threadIdx.x;
  const int lane = tid & 31;
  const int warp = tid >> 5;
  const int mw   = warp >> 2;   // 0..1 (32-row band)
  const int nw   = warp & 3;    // 0..3 (64-col band)
  const int lr   = lane >> 2;   // 0..7
  const int lc   = lane & 3;    // 0..3

  const int hp    = blockIdx.x & 3;     // head pair
  const int mtile = blockIdx.x >> 2;
  const int sbase = mtile * SPC;
  const long rbase = (long)sbase * 6;

  // hoisted per-head W bases (kills runtime head*k multiplies in prefetch)
  const __nv_bfloat16* wb0 = g_Wt + (size_t)(hp * 2)     * 262144;
  const __nv_bfloat16* wb1 = g_Wt + (size_t)(hp * 2 + 1) * 262144;

  // ---- per-lane ldmatrix address precompute (within-stage offsets)
  const int gq = lane >> 3, li = lane & 7;
  const int arow = mw * 32 + (gq & 1) * 8 + li;     // + mt*16
  const uint32_t aKb  = (uint32_t)((gq >> 1) * 16);
  const uint32_t aXor = (uint32_t)((arow & 7) << 4);
  const uint32_t aOff0 = (uint32_t)(arow * 128);
  const uint32_t aOff1 = aOff0 + 16 * 128;
  const int brow = nw * 64 + (gq >> 1) * 8 + li;    // + nt*16
  const uint32_t bKb  = (uint32_t)((gq & 1) * 16);
  const uint32_t bXor = (uint32_t)((brow & 7) << 4);
  const uint32_t bOffB = (uint32_t)(BOFF + brow * 128);

  auto loadA = [&](int c, int stage) {
    const int kc0 = c * 64;
#pragma unroll
    for (int it = 0; it < 2; it++) {
      const int v = tid + it * 256;         // 0..511
      const int r = v >> 3, ch = v & 7;     // row 0..63
      const long gr = rbase + r;
      const bool ok = (r < 60) && (gr < kRows);
      const uint32_t dst = sb + stage * STAGE + (uint32_t)(r * 128) +
                           (uint32_t)((ch * 16) ^ ((r & 7) << 4));
      cpa16(dst, g_Ebf + (ok ? gr : 0) * 1024 + kc0 + ch * 8, ok ? 16 : 0);
    }
  };
  auto loadB = [&](int c, int stage, const __nv_bfloat16* wbase) {
    const int kc0 = c * 64;
#pragma unroll
    for (int it = 0; it < 8; it++) {
      const int v = tid + it * 256;         // 0..2047
      const int n = v >> 3, ch = v & 7;
      const uint32_t dst = sb + stage * STAGE + BOFF + (uint32_t)(n * 128) +
                           (uint32_t)((ch * 16) ^ ((n & 7) << 4));
      cpa16(dst, wbase + n * 1024 + kc0 + ch * 8, 16);
    }
  };

  float acc[2][8][4];
#pragma unroll
  for (int a0 = 0; a0 < 2; a0++)
#pragma unroll
    for (int a1 = 0; a1 < 8; a1++)
#pragma unroll
      for (int a2 = 0; a2 < 4; a2++) acc[a0][a1][a2] = 0.f;

  // prime continuous pipeline (t = 0, 1 of 32)
  loadA(0, 0); loadB(0, 0, wb0);
  asm volatile("cp.async.commit_group;" ::: "memory");
  loadA(1, 1); loadB(1, 1, wb0);
  asm volatile("cp.async.commit_group;" ::: "memory");

  uint32_t aF[2][2][4];   // [ks parity][m tile][4]
  uint32_t bF[2][4];      // [nt parity][4]
  const float kInvSqrt = 0.08838834764831845f;  // 1/sqrt(128)

  for (int u = 0; u < 2; u++) {
    const int head = hp * 2 + u;
    bia[tid] = (tid < 128) ? bq[head * 128 + tid] : bk[head * 128 + tid - 128];

    for (int c = 0; c < 16; c++) {
      const int t = u * 16 + c;
      if (t < TCH - 1) asm volatile("cp.async.wait_group 1;" ::: "memory");
      else             asm volatile("cp.async.wait_group 0;" ::: "memory");
      __syncthreads();

      const uint32_t stb = sb + (uint32_t)((t & 1) * STAGE);

      // prologue fragments for ks=0, nt=0
      ldsm4(aF[0][0], stb + aOff0 + (aKb ^ aXor));
      ldsm4(aF[0][1], stb + aOff1 + (aKb ^ aXor));
      ldsm4(bF[0],    stb + bOffB + (bKb ^ bXor));

#pragma unroll
      for (int ks = 0; ks < 4; ks++) {
        const int kcur = ks & 1, knxt = kcur ^ 1;
#pragma unroll
        for (int nt = 0; nt < 4; nt++) {
          const int cur = nt & 1, nxt = cur ^ 1;
          if (nt < 3) {
            const uint32_t bkb = (uint32_t)(ks * 32) + bKb;
            ldsm4(bF[nxt], stb + bOffB + (uint32_t)((nt + 1) * 16 * 128) + (bkb ^ bXor));
          } else if (ks < 3) {
            const uint32_t akb2 = (uint32_t)((ks + 1) * 32) + aKb;
            ldsm4(aF[knxt][0], stb + aOff0 + (akb2 ^ aXor));
            ldsm4(aF[knxt][1], stb + aOff1 + (akb2 ^ aXor));
            const uint32_t bkb2 = (uint32_t)((ks + 1) * 32) + bKb;
            ldsm4(bF[nxt], stb + bOffB + (bkb2 ^ bXor));
          }
          mma_bf16(acc[0][nt * 2],     aF[kcur][0], bF[cur]);
          mma_bf16(acc[0][nt * 2 + 1], aF[kcur][0], bF[cur] + 2);
          mma_bf16(acc[1][nt * 2],     aF[kcur][1], bF[cur]);
          mma_bf16(acc[1][nt * 2 + 1], aF[kcur][1], bF[cur] + 2);
        }
      }
      __syncthreads();   // all warps done reading stage t&1
      if (t + 2 < TCH) {
        const int t2 = t + 2;
        const int cn = t2 & 15;
        const __nv_bfloat16* wn = (t2 >= 16) ? wb1 : wb0;
        loadA(cn, t2 & 1);
        loadB(cn, t2 & 1, wn);
        asm volatile("cp.async.commit_group;" ::: "memory");
      }
    }

    // ---- dump Q|K (+bias) into bf16 qk region (DMA for next head keeps running)
#pragma unroll
    for (int mt = 0; mt < 2; mt++)
#pragma unroll
      for (int nt = 0; nt < 8; nt++) {
        const int r0 = mw * 32 + mt * 16 + lr;   // <= 55
        const int c0 = nw * 64 + nt * 8 + 2 * lc;
        *(__nv_bfloat162*)&qkb[r0 * QKS2 + c0] =
            __floats2bfloat162_rn(acc[mt][nt][0] + bia[c0], acc[mt][nt][1] + bia[c0 + 1]);
        if (r0 + 8 < 60)
          *(__nv_bfloat162*)&qkb[(r0 + 8) * QKS2 + c0] =
              __floats2bfloat162_rn(acc[mt][nt][2] + bia[c0], acc[mt][nt][3] + bia[c0 + 1]);
      }
    // zero acc for next head
#pragma unroll
    for (int a0 = 0; a0 < 2; a0++)
#pragma unroll
      for (int a1 = 0; a1 < 8; a1++)
#pragma unroll
        for (int a2 = 0; a2 < 4; a2++) acc[a0][a1][a2] = 0.f;
    __syncthreads();

    // ---- scores: one warp per sample (bf16 qk reads)
    for (int s = warp; s < SPC; s += 8) {
      const int sg = sbase + s;
      if (sg >= kSamples) continue;
      float qv[6][4], kv[6][4];
#pragma unroll
      for (int i = 0; i < 6; i++) {
        const __nv_bfloat16* qp = qkb + (s * 6 + i) * QKS2 + lane;
#pragma unroll
        for (int uu = 0; uu < 4; uu++) {
          qv[i][uu] = __bfloat162float(qp[32 * uu]);
          kv[i][uu] = __bfloat162float(qp[128 + 32 * uu]);
        }
      }
#pragma unroll
      for (int i = 0; i < 6; i++)
#pragma unroll
        for (int j = 0; j < 6; j++) {
          float p = qv[i][0] * kv[j][0] + qv[i][1] * kv[j][1]
                  + qv[i][2] * kv[j][2] + qv[i][3] * kv[j][3];
#pragma unroll
          for (int o = 16; o > 0; o >>= 1) p += __shfl_xor_sync(0xffffffffu, p, o);
          if (lane == 0) sc[s * 36 + i * 6 + j] = p;
        }
    }
    __syncthreads();

    // ---- gated softmax; write attention; keep A in smem
    if (tid < SPC * 6) {
      const int s = tid / 6, i = tid % 6;
      const int sg = sbase + s;
      if (sg < kSamples) {
        float l[6], mx = -1e30f;
#pragma unroll
        for (int j = 0; j < 6; j++) {
          l[j] = sc[s * 36 + i * 6 + j] * kInvSqrt * g_gate[sg * 6 + j];
          mx = fmaxf(mx, l[j]);
        }
        float sum = 0.f;
#pragma unroll
        for (int j = 0; j < 6; j++) { l[j] = expf(l[j] - mx); sum += l[j]; }
        const float rcp = 1.f / sum;
        float* ao = att + (((long)sg * 8 + head) * 6 + i) * 6;
#pragma unroll
        for (int j = 0; j < 6; j++) {
          const float a = l[j] * rcp;
          ao[j] = a;
          sc[s * 36 + i * 6 + j] = a;
        }
      }
    }
    __syncthreads();

    // ---- context: ctx[6s+i, head*128+cc] = sum_j A[i][j] * E[6s+j, head*128+cc]
    for (int idx = tid; idx < SPC * 128; idx += 256) {
      const int s = idx >> 7;
      const int cc = idx & 127;
      const int sg = sbase + s;
      if (sg >= kSamples) continue;
      const float* ep = emb + (long)sg * 6 * 1024 + head * 128 + cc;
      float e[6];
#pragma unroll
      for (int j = 0; j < 6; j++) e[j] = ep[(long)j * 1024];
#pragma unroll
      for (int i = 0; i < 6; i++) {
        float v = 0.f;
#pragma unroll
        for (int j = 0; j < 6; j++) v = fmaf(sc[s * 36 + i * 6 + j], e[j], v);
        ctx[((long)sg * 6 + i) * 1024 + head * 128 + cc] = v;
      }
    }
    __syncthreads();
  }
}

extern "C" void kernel_launch(void* const* d_in, const int* in_sizes, int n_in,
                              void* d_out, int out_size) {
  (void)in_sizes; (void)n_in; (void)out_size;
  const float* emb = (const float*)d_in[0];
  const float* ac  = (const float*)d_in[1];
  const float* Wk  = (const float*)d_in[2];
  const float* bk  = (const float*)d_in[3];
  const float* Wq  = (const float*)d_in[4];
  const float* bq  = (const float*)d_in[5];
  const float* Wg  = (const float*)d_in[6];
  const float* bg  = (const float*)d_in[7];

  float* ctx = (float*)d_out;
  float* att = ctx + kRows * 1024L;

  conv_e_kernel<<<8192, 256>>>(emb);
  conv_w_kernel<<<1024, 256>>>(Wq, Wk);
  gate_kernel<<<384, 256>>>(ac, Wg, bg);

  cudaFuncSetAttribute(attn_main_kernel,
                       cudaFuncAttributeMaxDynamicSharedMemorySize, SMEM_TOTAL);
  attn_main_kernel<<<MTILES * 4, 256, SMEM_TOTAL>>>(emb, bk, bq, ctx, att);
}

// round 16
// speedup vs baseline: 1.0887x; 1.0887x over previous
#include <cuda_runtime.h>
#include <cuda_bf16.h>
#include <cstdint>

// ---------------- device scratch (globals — allowed) ----------------
__device__ __nv_bfloat16 g_Ebf[98304UL * 1024];   // E in bf16, row-major
__device__ __nv_bfloat16 g_Wt[8 * 256 * 1024];    // [head][n (Q0..127|K128..255)][k]
__device__ float         g_gate[16384 * 6];

namespace {

constexpr int  kSamples = 16384;
constexpr long kRows    = 98304;               // 16384*6
constexpr int  CHUNKS   = 16;                  // K=1024 / 64
constexpr int  SPC      = 10;                  // samples per CTA tile (60 rows, pad 64)
constexpr int  MTILES   = (kSamples + SPC - 1) / SPC;  // 1639
constexpr int  STAGE    = 40960;               // A 8KB + B 32KB
constexpr int  BOFF     = 8192;                // B within stage
constexpr uint32_t AUX  = 81920;               // after 2 stages
constexpr uint32_t BIASO= AUX;                 // 256 f32
constexpr uint32_t SCO  = AUX + 1024;          // 360 f32
constexpr int  SMEM_TOTAL = 84480;             // 2 CTAs/SM
constexpr int  QKS = 257;                      // qk stride (floats); qk aliases stages

__device__ __forceinline__ uint32_t smem_u32(const void* p) {
  return (uint32_t)__cvta_generic_to_shared(p);
}
__device__ __forceinline__ void cpa16(uint32_t dst, const void* src, int sz) {
  asm volatile("cp.async.cg.shared.global [%0], [%1], 16, %2;\n"
               :: "r"(dst), "l"(src), "r"(sz));
}
__device__ __forceinline__ void ldsm4(uint32_t* r, uint32_t addr) {
  asm volatile("ldmatrix.sync.aligned.m8n8.x4.shared.b16 {%0,%1,%2,%3}, [%4];"
               : "=r"(r[0]), "=r"(r[1]), "=r"(r[2]), "=r"(r[3]) : "r"(addr));
}
__device__ __forceinline__ void mma_bf16(float* d, const uint32_t* a, const uint32_t* b) {
  asm volatile(
      "mma.sync.aligned.m16n8k16.row.col.f32.bf16.bf16.f32 "
      "{%0,%1,%2,%3}, {%4,%5,%6,%7}, {%8,%9}, {%0,%1,%2,%3};\n"
      : "+f"(d[0]), "+f"(d[1]), "+f"(d[2]), "+f"(d[3])
      : "r"(a[0]), "r"(a[1]), "r"(a[2]), "r"(a[3]), "r"(b[0]), "r"(b[1]));
}

}  // namespace

// ---------------- pre-pass kernels ----------------
__global__ void conv_e_kernel(const float* __restrict__ emb) {
  const long total = kRows * 1024 / 8;
  for (long i = blockIdx.x * 256L + threadIdx.x; i < total; i += (long)gridDim.x * 256) {
    const float4* s = (const float4*)emb + i * 2;
    float4 a = s[0], b = s[1];
    __nv_bfloat162* o = (__nv_bfloat162*)g_Ebf + i * 4;
    o[0] = __floats2bfloat162_rn(a.x, a.y);
    o[1] = __floats2bfloat162_rn(a.z, a.w);
    o[2] = __floats2bfloat162_rn(b.x, b.y);
    o[3] = __floats2bfloat162_rn(b.z, b.w);
  }
}

__global__ void conv_w_kernel(const float* __restrict__ Wq, const float* __restrict__ Wk) {
  const int idx = blockIdx.x * 256 + threadIdx.x;  // 262144 total
  const int h  = idx >> 15;
  const int n  = (idx >> 7) & 255;
  const int k0 = (idx & 127) * 8;
  const float* W = (n < 128) ? Wq : Wk;
  const int col = h * 128 + (n & 127);
  __nv_bfloat16* o = g_Wt + ((long)(h * 256 + n)) * 1024 + k0;
#pragma unroll
  for (int t = 0; t < 8; t++) o[t] = __float2bfloat16(W[(long)(k0 + t) * 1024 + col]);
}

__global__ void gate_kernel(const float* __restrict__ ac, const float* __restrict__ Wg,
                            const float* __restrict__ bg) {
  const int idx = blockIdx.x * 256 + threadIdx.x;  // 98304
  const int s = idx / 6, j = idx % 6;
  const float* ap = ac + (long)s * 128;
  float g = bg[j];
#pragma unroll 8
  for (int c = 0; c < 128; c++) g = fmaf(ap[c], Wg[c * 6 + j], g);
  g_gate[idx] = g;
}

// ---------------- main fused kernel: one (mtile, head) per CTA, 2 CTAs/SM ----------------
__global__ void __launch_bounds__(256, 2)
attn_main_kernel(const float* __restrict__ emb, const float* __restrict__ bk,
                 const float* __restrict__ bq, float* __restrict__ ctx,
                 float* __restrict__ att) {
  extern __shared__ char smc[];
  const uint32_t sb = smem_u32(smc);
  float* qk  = (float*)smc;              // 64 x 257 f32, aliases stage area post-GEMM
  float* bia = (float*)(smc + BIASO);
  float* sc  = (float*)(smc + SCO);

  const int tid  = threadIdx.x;
  const int lane = tid & 31;
  const int warp = tid >> 5;
  const int mw   = warp >> 2;   // 0..1 (32-row band)
  const int nw   = warp & 3;    // 0..3 (64-col band)
  const int lr   = lane >> 2;   // 0..7
  const int lc   = lane & 3;    // 0..3

  const int head  = blockIdx.x & 7;
  const int mtile = blockIdx.x >> 3;
  const int sbase = mtile * SPC;

  // hoisted byte-base pointers; all per-cp.async offsets are 32-bit
  const char* ab = (const char*)g_Ebf + (uint32_t)(sbase * 6) * 2048u;   // < 2^31
  const char* wb = (const char*)g_Wt + (size_t)head * 524288u;           // 256*1024*2

  bia[tid] = (tid < 128) ? bq[head * 128 + tid] : bk[head * 128 + tid - 128];

  // ---- per-lane ldmatrix address precompute (within-stage offsets)
  const int gq = lane >> 3, li = lane & 7;
  const int arow = mw * 32 + (gq & 1) * 8 + li;     // + mt*16
  const uint32_t aKb  = (uint32_t)((gq >> 1) * 16);
  const uint32_t aXor = (uint32_t)((arow & 7) << 4);
  const uint32_t aOff0 = (uint32_t)(arow * 128);
  const uint32_t aOff1 = aOff0 + 16 * 128;
  const int brow = nw * 64 + (gq >> 1) * 8 + li;    // + nt*16
  const uint32_t bKb  = (uint32_t)((gq & 1) * 16);
  const uint32_t bXor = (uint32_t)((brow & 7) << 4);
  const uint32_t bOffB = (uint32_t)(BOFF + brow * 128);

  auto loadA = [&](int c, int stage) {
    const uint32_t kb = (uint32_t)(c * 128);   // kc0 bytes
#pragma unroll
    for (int it = 0; it < 2; it++) {
      const int v = tid + it * 256;            // 0..511
      const int r = v >> 3, ch = v & 7;        // row 0..63
      const bool ok = (r < 60) && ((long)(sbase * 6 + r) < kRows);
      const uint32_t dst = sb + stage * STAGE + (uint32_t)(r * 128) +
                           (uint32_t)((ch * 16) ^ ((r & 7) << 4));
      const uint32_t soff = ok ? (uint32_t)(r * 2048 + ch * 16) : 0u;
      cpa16(dst, ab + soff + kb, ok ? 16 : 0);
    }
  };
  auto loadB = [&](int c, int stage) {
    const uint32_t kb = (uint32_t)(c * 128);
#pragma unroll
    for (int it = 0; it < 8; it++) {
      const int v = tid + it * 256;            // 0..2047
      const int n = v >> 3, ch = v & 7;
      const uint32_t dst = sb + stage * STAGE + BOFF + (uint32_t)(n * 128) +
                           (uint32_t)((ch * 16) ^ ((n & 7) << 4));
      cpa16(dst, wb + (uint32_t)(n * 2048 + ch * 16) + kb, 16);
    }
  };

  float acc[2][8][4];
#pragma unroll
  for (int a0 = 0; a0 < 2; a0++)
#pragma unroll
    for (int a1 = 0; a1 < 8; a1++)
#pragma unroll
      for (int a2 = 0; a2 < 4; a2++) acc[a0][a1][a2] = 0.f;

  loadA(0, 0); loadB(0, 0);
  asm volatile("cp.async.commit_group;" ::: "memory");
  loadA(1, 1); loadB(1, 1);
  asm volatile("cp.async.commit_group;" ::: "memory");

  uint32_t aF[2][2][4];   // [ks parity][m tile][4]
  uint32_t bF[2][4];      // [nt parity][4]

  for (int c = 0; c < CHUNKS; c++) {
    if (c < CHUNKS - 1) asm volatile("cp.async.wait_group 1;" ::: "memory");
    else                asm volatile("cp.async.wait_group 0;" ::: "memory");
    __syncthreads();

    const uint32_t stb = sb + (uint32_t)((c & 1) * STAGE);

    // prologue fragments for ks=0, nt=0
    ldsm4(aF[0][0], stb + aOff0 + (aKb ^ aXor));
    ldsm4(aF[0][1], stb + aOff1 + (aKb ^ aXor));
    ldsm4(bF[0],    stb + bOffB + (bKb ^ bXor));

#pragma unroll
    for (int ks = 0; ks < 4; ks++) {
      const int kcur = ks & 1, knxt = kcur ^ 1;
#pragma unroll
      for (int nt = 0; nt < 4; nt++) {
        const int cur = nt & 1, nxt = cur ^ 1;
        if (nt < 3) {
          const uint32_t bkb = (uint32_t)(ks * 32) + bKb;
          ldsm4(bF[nxt], stb + bOffB + (uint32_t)((nt + 1) * 16 * 128) + (bkb ^ bXor));
        } else if (ks < 3) {
          const uint32_t akb2 = (uint32_t)((ks + 1) * 32) + aKb;
          ldsm4(aF[knxt][0], stb + aOff0 + (akb2 ^ aXor));
          ldsm4(aF[knxt][1], stb + aOff1 + (akb2 ^ aXor));
          const uint32_t bkb2 = (uint32_t)((ks + 1) * 32) + bKb;
          ldsm4(bF[nxt], stb + bOffB + (bkb2 ^ bXor));
        }
        mma_bf16(acc[0][nt * 2],     aF[kcur][0], bF[cur]);
        mma_bf16(acc[0][nt * 2 + 1], aF[kcur][0], bF[cur] + 2);
        mma_bf16(acc[1][nt * 2],     aF[kcur][1], bF[cur]);
        mma_bf16(acc[1][nt * 2 + 1], aF[kcur][1], bF[cur] + 2);
      }
    }
    __syncthreads();   // all warps done reading stage c&1
    if (c + 2 < CHUNKS) {
      loadA(c + 2, c & 1);
      loadB(c + 2, c & 1);
      asm volatile("cp.async.commit_group;" ::: "memory");
    }
  }
  // stage area now reusable as qk (last sync above covers it)

  // ---- dump Q|K tile (+bias) into union smem
#pragma unroll
  for (int mt = 0; mt < 2; mt++)
#pragma unroll
    for (int nt = 0; nt < 8; nt++) {
      const int r0 = mw * 32 + mt * 16 + lr;
      const int c0 = nw * 64 + nt * 8 + 2 * lc;
      qk[r0 * QKS + c0]           = acc[mt][nt][0] + bia[c0];
      qk[r0 * QKS + c0 + 1]       = acc[mt][nt][1] + bia[c0 + 1];
      qk[(r0 + 8) * QKS + c0]     = acc[mt][nt][2] + bia[c0];
      qk[(r0 + 8) * QKS + c0 + 1] = acc[mt][nt][3] + bia[c0 + 1];
    }
  __syncthreads();

  const float kInvSqrt = 0.08838834764831845f;  // 1/sqrt(128)

  // ---- scores: one warp per sample
  for (int s = warp; s < SPC; s += 8) {
    const int sg = sbase + s;
    if (sg >= kSamples) continue;
    float qv[6][4], kv[6][4];
#pragma unroll
    for (int i = 0; i < 6; i++) {
      const float* qp = qk + (s * 6 + i) * QKS + lane;
#pragma unroll
      for (int u = 0; u < 4; u++) {
        qv[i][u] = qp[32 * u];
        kv[i][u] = qp[128 + 32 * u];
      }
    }
#pragma unroll
    for (int i = 0; i < 6; i++)
#pragma unroll
      for (int j = 0; j < 6; j++) {
        float p = qv[i][0] * kv[j][0] + qv[i][1] * kv[j][1]
                + qv[i][2] * kv[j][2] + qv[i][3] * kv[j][3];
#pragma unroll
        for (int o = 16; o > 0; o >>= 1) p += __shfl_xor_sync(0xffffffffu, p, o);
        if (lane == 0) sc[s * 36 + i * 6 + j] = p;
      }
  }
  __syncthreads();

  // ---- gated softmax; write attention; keep A in smem
  if (tid < SPC * 6) {
    const int s = tid / 6, i = tid % 6;
    const int sg = sbase + s;
    if (sg < kSamples) {
      float l[6], mx = -1e30f;
#pragma unroll
      for (int j = 0; j < 6; j++) {
        l[j] = sc[s * 36 + i * 6 + j] * kInvSqrt * g_gate[sg * 6 + j];
        mx = fmaxf(mx, l[j]);
      }
      float sum = 0.f;
#pragma unroll
      for (int j = 0; j < 6; j++) { l[j] = expf(l[j] - mx); sum += l[j]; }
      const float rcp = 1.f / sum;
      float* ao = att + (((long)sg * 8 + head) * 6 + i) * 6;
#pragma unroll
      for (int j = 0; j < 6; j++) {
        const float a = l[j] * rcp;
        ao[j] = a;
        sc[s * 36 + i * 6 + j] = a;
      }
    }
  }
  __syncthreads();

  // ---- context: ctx[6s+i, head*128+cc] = sum_j A[i][j] * E[6s+j, head*128+cc]
  for (int idx = tid; idx < SPC * 128; idx += 256) {
    const int s = idx >> 7;
    const int cc = idx & 127;
    const int sg = sbase + s;
    if (sg >= kSamples) continue;
    const float* ep = emb + (long)sg * 6 * 1024 + head * 128 + cc;
    float e[6];
#pragma unroll
    for (int j = 0; j < 6; j++) e[j] = ep[(long)j * 1024];
#pragma unroll
    for (int i = 0; i < 6; i++) {
      float v = 0.f;
#pragma unroll
      for (int j = 0; j < 6; j++) v = fmaf(sc[s * 36 + i * 6 + j], e[j], v);
      ctx[((long)sg * 6 + i) * 1024 + head * 128 + cc] = v;
    }
  }
}

extern "C" void kernel_launch(void* const* d_in, const int* in_sizes, int n_in,
                              void* d_out, int out_size) {
  (void)in_sizes; (void)n_in; (void)out_size;
  const float* emb = (const float*)d_in[0];
  const float* ac  = (const float*)d_in[1];
  const float* Wk  = (const float*)d_in[2];
  const float* bk  = (const float*)d_in[3];
  const float* Wq  = (const float*)d_in[4];
  const float* bq  = (const float*)d_in[5];
  const float* Wg  = (const float*)d_in[6];
  const float* bg  = (const float*)d_in[7];

  float* ctx = (float*)d_out;
  float* att = ctx + kRows * 1024L;

  conv_e_kernel<<<8192, 256>>>(emb);
  conv_w_kernel<<<1024, 256>>>(Wq, Wk);
  gate_kernel<<<384, 256>>>(ac, Wg, bg);

  cudaFuncSetAttribute(attn_main_kernel,
                       cudaFuncAttributeMaxDynamicSharedMemorySize, SMEM_TOTAL);
  attn_main_kernel<<<MTILES * 8, 256, SMEM_TOTAL>>>(emb, bk, bq, ctx, att);
}